// round 13
// baseline (speedup 1.0000x reference)
#include <cuda_runtime.h>
#include <cuda_bf16.h>

#define NN    65536
#define NGR   32768
#define HH    64
#define BB    64
#define MAXD  10
#define BKT   128      // bucket capacity per (type,node); max real degree ~70
#define ZR    NN       // zero-row node id (padding target)

// ---- scratch: device globals (no allocation allowed) ----
__device__ __align__(16) float g_h [(size_t)(NN + 1) * HH];   // ping (+ zero row)
__device__ __align__(16) float g_h2[(size_t)(NN + 1) * HH];   // pong (+ zero row)
__device__ __align__(16) int   g_bkt[(size_t)4 * NGR * BKT];  // 64MB dst-bucketed src ids
__device__ int   g_cnt[4][NGR];                               // per-conv-type receive degree
__device__ float g_pooled[BB * HH];

// ---------------- init: pad buckets with ZR, zero counters/pooled/zero-rows ----------------
__global__ void init_kernel() {
    int gid = blockIdx.x * blockDim.x + threadIdx.x;
    const int nbq = 4 * NGR * BKT / 4;
    if (gid < nbq) {
        ((int4*)g_bkt)[gid] = make_int4(ZR, ZR, ZR, ZR);
    } else {
        int r = gid - nbq;
        if (r < 4 * NGR) ((int*)g_cnt)[r] = 0;
        else if (r < 4 * NGR + BB * HH) g_pooled[r - 4 * NGR] = 0.f;
        else if (r < 4 * NGR + BB * HH + HH) {
            int z = r - 4 * NGR - BB * HH;
            g_h [(size_t)ZR * HH + z] = 0.f;
            g_h2[(size_t)ZR * HH + z] = 0.f;
        }
    }
}

// ---------------- single pass: bucket all 4 edge sets ----------------
__global__ void fill_all_kernel(const int* __restrict__ e0, const int* __restrict__ e1,
                                const int* __restrict__ e2, const int* __restrict__ e3,
                                int E0, int E1, int E2, int E3) {
    int e = blockIdx.x * blockDim.x + threadIdx.x;
    const int* ei; int E, t, base;
    if (e < E0)              { ei = e0; E = E0; t = 0; base = 0;   }
    else if ((e -= E0) < E1) { ei = e1; E = E1; t = 1; base = NGR; }
    else if ((e -= E1) < E2) { ei = e2; E = E2; t = 2; base = NGR; }
    else if ((e -= E2) < E3) { ei = e3; E = E3; t = 3; base = 0;   }
    else return;
    int src = __ldg(ei + e);
    int dst = __ldg(ei + E + e);
    int li  = dst - base;
    int slot = atomicAdd(&g_cnt[t][li], 1);
    if (slot < BKT) g_bkt[((size_t)(t * NGR + li) << 7) + slot] = src;
}

// ---------------- embed: h = x @ W(32x64) + b ----------------
__global__ void embed_kernel(const float* __restrict__ x,
                             const float* __restrict__ W,
                             const float* __restrict__ b) {
    int node = blockIdx.x * 8 + (threadIdx.x >> 5);
    int lane = threadIdx.x & 31;
    float xv = x[(size_t)node * 32 + lane];
    int c = lane * 2;
    float2 acc = make_float2(b[c], b[c + 1]);
#pragma unroll 8
    for (int k = 0; k < 32; k++) {
        float xk = __shfl_sync(0xffffffffu, xv, k);
        float2 w = *(const float2*)(W + k * 64 + c);
        acc.x += xk * w.x;
        acc.y += xk * w.y;
    }
    *(float2*)(g_h + (size_t)node * 64 + c) = acc;
}

// ---------------- relu on both current halves ----------------
__global__ void relu2_kernel(float* bg, float* bs) {
    int gid = blockIdx.x * blockDim.x + threadIdx.x;   // NN*16 quads
    float* buf = (gid < NGR * 16) ? bg : bs;           // halves at natural offsets
    float4* p = ((float4*)buf) + gid;
    float4 v = *p;
    v.x = fmaxf(v.x, 0.f); v.y = fmaxf(v.y, 0.f);
    v.z = fmaxf(v.z, 0.f); v.w = fmaxf(v.w, 0.f);
    *p = v;
}

// ---- single-node conv (fallback path; float2 layout) ----
__device__ __forceinline__ void conv_one(const float2* __restrict__ in2,
                                         const float2* __restrict__ ind2,
                                         float2* __restrict__ out2,
                                         const int* __restrict__ ep, int n, int lane,
                                         int node,
                                         const float* __restrict__ Wl,
                                         const float* __restrict__ bl,
                                         const float* __restrict__ Wr) {
    float2 a = make_float2(0.f, 0.f);
    int nr = (n + 1) & ~1;              // padded slots read the zero row
    for (int e = 0; e < nr; e += 2) {
        int s0 = __ldg(ep + e), s1 = __ldg(ep + e + 1);
        float2 v0 = in2[(size_t)s0 * 32 + lane];
        float2 v1 = in2[(size_t)s1 * 32 + lane];
        a.x += v0.x + v1.x;
        a.y += v0.y + v1.y;
    }
    int d = n > MAXD ? MAXD : n;
    const float2* wl2 = (const float2*)(Wl + (size_t)d * 4096);
    const float2* wr2 = (const float2*)(Wr + (size_t)d * 4096);
    float2 h = ind2[(size_t)node * 32 + lane];
    float2 acc = ((const float2*)(bl + (size_t)d * 64))[lane];
#pragma unroll 8
    for (int j = 0; j < 32; j++) {
        float2 wle = wl2[(2 * j) * 32 + lane];
        float2 wlo = wl2[(2 * j + 1) * 32 + lane];
        float2 wre = wr2[(2 * j) * 32 + lane];
        float2 wro = wr2[(2 * j + 1) * 32 + lane];
        float ax = __shfl_sync(0xffffffffu, a.x, j);
        float ay = __shfl_sync(0xffffffffu, a.y, j);
        float hx = __shfl_sync(0xffffffffu, h.x, j);
        float hy = __shfl_sync(0xffffffffu, h.y, j);
        acc.x += ax * wle.x + ay * wlo.x + hx * wre.x + hy * wro.x;
        acc.y += ax * wle.y + ay * wlo.y + hx * wre.y + hy * wro.y;
    }
    out2[(size_t)node * 32 + lane] = acc;
}

// ---- fused conv: 4 nodes/warp, idx prefetch + float2 gather, shared weights ----
__global__ void __launch_bounds__(256, 5)
conv_kernel(const float* __restrict__ in_src,
            const float* __restrict__ in_dst,
            float* __restrict__ out,
            int t, int base, int copy,
            const float* __restrict__ Wl,
            const float* __restrict__ bl,
            const float* __restrict__ Wr) {
    int warp = blockIdx.x * 8 + (threadIdx.x >> 5);
    int lane = threadIdx.x & 31;
    int li0 = warp * 4;                 // 4 consecutive local nodes
    const float2* in2  = (const float2*)in_src;
    const float2* ind2 = (const float2*)in_dst;
    float2*       out2 = (float2*)out;
    size_t bkt0 = ((size_t)(t * NGR + li0)) << 7;
    int n[4], d[4];
    bool allpos = true;
#pragma unroll
    for (int i = 0; i < 4; i++) {
        int nn = g_cnt[t][li0 + i];
        if (nn > BKT) nn = BKT;
        n[i] = nn;
        d[i] = nn > MAXD ? MAXD : nn;
        allpos &= (nn > 0);
    }
    if (allpos && d[0] == d[1] && d[0] == d[2] && d[0] == d[3]) {
        // ---- fast path: shared degree bucket ----
        float2 a0 = make_float2(0.f, 0.f), a1 = a0, a2 = a0, a3 = a0;
        int nm = max(max(n[0], n[1]), max(n[2], n[3]));
        int nm8 = (nm + 7) & ~7;        // round to 8; padded slots hit the zero row
        for (int c0 = 0; c0 < nm8; c0 += 32) {
            // warp-cooperative index prefetch: lane l holds slot c0+l of each bucket
            int i0 = __ldg(g_bkt + bkt0 +       c0 + lane);
            int i1 = __ldg(g_bkt + bkt0 + 128 + c0 + lane);
            int i2 = __ldg(g_bkt + bkt0 + 256 + c0 + lane);
            int i3 = __ldg(g_bkt + bkt0 + 384 + c0 + lane);
            int lim = nm8 - c0; if (lim > 32) lim = 32;
#pragma unroll 8
            for (int e = 0; e < lim; e++) {
                int s0 = __shfl_sync(0xffffffffu, i0, e);
                int s1 = __shfl_sync(0xffffffffu, i1, e);
                int s2 = __shfl_sync(0xffffffffu, i2, e);
                int s3 = __shfl_sync(0xffffffffu, i3, e);
                float2 v0 = in2[(size_t)s0 * 32 + lane];
                float2 v1 = in2[(size_t)s1 * 32 + lane];
                float2 v2 = in2[(size_t)s2 * 32 + lane];
                float2 v3 = in2[(size_t)s3 * 32 + lane];
                a0.x += v0.x; a0.y += v0.y;
                a1.x += v1.x; a1.y += v1.y;
                a2.x += v2.x; a2.y += v2.y;
                a3.x += v3.x; a3.y += v3.y;
            }
        }
        int dd = d[0];
        const float2* wl2 = (const float2*)(Wl + (size_t)dd * 4096);
        const float2* wr2 = (const float2*)(Wr + (size_t)dd * 4096);
        float2 bv = ((const float2*)(bl + (size_t)dd * 64))[lane];
        float2 acc[4] = {bv, bv, bv, bv};
        float2 hv[4];
#pragma unroll
        for (int i = 0; i < 4; i++)
            hv[i] = ind2[(size_t)(base + li0 + i) * 32 + lane];
        float2 av[4] = {a0, a1, a2, a3};
#pragma unroll 4
        for (int j = 0; j < 32; j++) {
            float2 wle = wl2[(2 * j) * 32 + lane];
            float2 wlo = wl2[(2 * j + 1) * 32 + lane];
            float2 wre = wr2[(2 * j) * 32 + lane];
            float2 wro = wr2[(2 * j + 1) * 32 + lane];
#pragma unroll
            for (int i = 0; i < 4; i++) {
                float ax = __shfl_sync(0xffffffffu, av[i].x, j);
                float ay = __shfl_sync(0xffffffffu, av[i].y, j);
                float hx = __shfl_sync(0xffffffffu, hv[i].x, j);
                float hy = __shfl_sync(0xffffffffu, hv[i].y, j);
                acc[i].x += ax * wle.x + ay * wlo.x + hx * wre.x + hy * wro.x;
                acc[i].y += ax * wle.y + ay * wlo.y + hx * wre.y + hy * wro.y;
            }
        }
#pragma unroll
        for (int i = 0; i < 4; i++)
            out2[(size_t)(base + li0 + i) * 32 + lane] = acc[i];
    } else {
        // ---- fallback: per node ----
        for (int i = 0; i < 4; i++) {
            int node = base + li0 + i;
            if (n[i] == 0) {
                if (copy) out2[(size_t)node * 32 + lane] = ind2[(size_t)node * 32 + lane];
                continue;
            }
            conv_one(in2, ind2, out2, g_bkt + bkt0 + i * 128, n[i], lane, node, Wl, bl, Wr);
        }
    }
}

// ---------------- pool over ground nodes (scalar f32 atomics) ----------------
__global__ void pool_kernel(const int* __restrict__ batch_idx, const float* __restrict__ buf) {
    int gid = blockIdx.x * blockDim.x + threadIdx.x;  // NG*64
    int i  = gid >> 6;
    int cc = gid & 63;
    int b = __ldg(batch_idx + i);
    atomicAdd(&g_pooled[b * 64 + cc], buf[(size_t)i * 64 + cc]);
}

// ---------------- head: out = relu(pooled@W1+b1) @ W2 + b2 ----------------
__global__ void head_kernel(const float* __restrict__ W1, const float* __restrict__ b1,
                            const float* __restrict__ W2, const float* __restrict__ b2,
                            float* __restrict__ out) {
    int bidx = blockIdx.x;
    int c = threadIdx.x;
    float acc = b1[c];
#pragma unroll 8
    for (int k = 0; k < 64; k++)
        acc += g_pooled[bidx * 64 + k] * W1[k * 64 + c];
    acc = fmaxf(acc, 0.f) * W2[c];
#pragma unroll
    for (int o = 16; o > 0; o >>= 1)
        acc += __shfl_down_sync(0xffffffffu, acc, o);
    __shared__ float s[2];
    if ((threadIdx.x & 31) == 0) s[threadIdx.x >> 5] = acc;
    __syncthreads();
    if (threadIdx.x == 0) out[bidx] = s[0] + s[1] + b2[0];
}

extern "C" void kernel_launch(void* const* d_in, const int* in_sizes, int n_in,
                              void* d_out, int out_size) {
    const float* x          = (const float*)d_in[0];
    const int*   edge_index = (const int*)d_in[1];   // JAX x64-disabled -> int32
    const int*   sub_ei     = (const int*)d_in[2];
    const int*   ns_ei      = (const int*)d_in[3];
    const int*   sn_ei      = (const int*)d_in[4];
    const int*   batch_idx  = (const int*)d_in[7];
    const float* embed_W = (const float*)d_in[8];
    const float* embed_b = (const float*)d_in[9];
    const float* Wl[4] = {(const float*)d_in[10], (const float*)d_in[13],
                          (const float*)d_in[16], (const float*)d_in[19]};
    const float* bl[4] = {(const float*)d_in[11], (const float*)d_in[14],
                          (const float*)d_in[17], (const float*)d_in[20]};
    const float* Wr[4] = {(const float*)d_in[12], (const float*)d_in[15],
                          (const float*)d_in[18], (const float*)d_in[21]};
    const float* W1 = (const float*)d_in[22];
    const float* b1 = (const float*)d_in[23];
    const float* W2 = (const float*)d_in[24];
    const float* b2 = (const float*)d_in[25];
    float* out = (float*)d_out;

    int E0 = in_sizes[1] / 2;   // ground   (t=0)
    int E1 = in_sizes[3] / 2;   // g2s      (t=1)
    int E2 = in_sizes[2] / 2;   // sub      (t=2)
    int E3 = in_sizes[4] / 2;   // s2g      (t=3)

    float* bufs[2];
    cudaGetSymbolAddress((void**)&bufs[0], g_h);
    cudaGetSymbolAddress((void**)&bufs[1], g_h2);

    const int initN = 4 * NGR * BKT / 4 + 4 * NGR + BB * HH + HH;
    init_kernel<<<(initN + 255) / 256, 256>>>();
    embed_kernel<<<NN / 8, 256>>>(x, embed_W, embed_b);
    fill_all_kernel<<<(E0 + E1 + E2 + E3 + 255) / 256, 256>>>(
        edge_index, ns_ei, sub_ei, sn_ei, E0, E1, E2, E3);

    int fg = 0, fs = 0;   // which buffer holds the current ground / sub half
    int bases[4] = {0, NGR, NGR, 0};
    for (int l = 0; l < 2; l++) {
        if (l) relu2_kernel<<<(NN * 16) / 256, 256>>>(bufs[fg], bufs[fs]);
        for (int t = 0; t < 4; t++) {
            size_t woff = (size_t)l * (MAXD + 1) * 64 * 64;
            size_t boff = (size_t)l * (MAXD + 1) * 64;
            const float* src; const float* dst; float* o; int copy;
            if (t == 0)      { src = bufs[fg]; dst = bufs[fg]; o = bufs[1 - fg]; copy = 1; }
            else if (t == 1) { src = bufs[fg]; dst = bufs[fs]; o = bufs[fs];     copy = 0; }
            else if (t == 2) { src = bufs[fs]; dst = bufs[fs]; o = bufs[1 - fs]; copy = 1; }
            else             { src = bufs[fs]; dst = bufs[fg]; o = bufs[fg];     copy = 0; }
            conv_kernel<<<NGR / 32, 256>>>(src, dst, o, t, bases[t], copy,
                                           Wl[t] + woff, bl[t] + boff, Wr[t] + woff);
            if (t == 0) fg ^= 1;
            if (t == 2) fs ^= 1;
        }
    }

    pool_kernel<<<(NGR * 64) / 256, 256>>>(batch_idx, bufs[fg]);
    head_kernel<<<BB, 64>>>(W1, b1, W2, b2, out);
}